// round 12
// baseline (speedup 1.0000x reference)
#include <cuda_runtime.h>
#include <cuda_fp16.h>
#include <math.h>
#include <stdint.h>

// ---------------- constants ----------------
#define N_ROIS   22500
#define IMGSZ    800.0f
#define MIN_SIZE 16.0f
#define PRE_NMS  2000
#define POST_NMS 128
#define IOU_TH   0.7f
#define FEAT_C   512
#define FEAT_HW  50
#define D_IN     25088   // 512*7*7
#define D_H      4096
#define NC       21
#define SORT_N   4096

#define OFF_DELTAS 2688
#define OFF_ROIS   13440

// ---------------- device scratch ----------------
__device__ float              g_featT[FEAT_HW * FEAT_HW * FEAT_C];
__device__ __align__(16) __half g_A1[POST_NMS * D_IN];   // pooled, fp16
__device__ __align__(16) __half g_A2[POST_NMS * D_H];    // h1, fp16
__device__ float              g_part[8 * POST_NMS * D_H];   // split-K partials (16MB)
__device__ float              g_h2[POST_NMS * D_H];
__device__ unsigned long long g_keys[N_ROIS];
__device__ int                g_hist[65536];
__device__ int                g_hist256[256];
__device__ int                g_threshBin;
__device__ int                g_cnt;
__device__ unsigned long long g_cand[SORT_N];
__device__ float              g_boxes[PRE_NMS * 4];
__device__ unsigned long long g_mask[PRE_NMS * 32];
__device__ int                g_keep[POST_NMS];
__device__ float              g_roisKept[POST_NMS * 4];

// ================= helpers =================
__device__ __forceinline__ uint32_t smem_u32(const void* p) {
    uint32_t a;
    asm("{ .reg .u64 t; cvta.to.shared.u64 t, %1; cvt.u32.u64 %0, t; }" : "=r"(a) : "l"(p));
    return a;
}
__device__ __forceinline__ void sts64(uint32_t a, uint32_t w0, uint32_t w1) {
    asm volatile("st.shared.v2.b32 [%0], {%1,%2};" :: "r"(a), "r"(w0), "r"(w1) : "memory");
}
__device__ __forceinline__ void cpasync16(uint32_t saddr, const void* g) {
    asm volatile("cp.async.cg.shared.global [%0], [%1], 16;" :: "r"(saddr), "l"(g) : "memory");
}
__device__ __forceinline__ void cpasync8(uint32_t saddr, const void* g) {
    asm volatile("cp.async.ca.shared.global [%0], [%1], 8;" :: "r"(saddr), "l"(g) : "memory");
}
__device__ __forceinline__ void cp_commit() {
    asm volatile("cp.async.commit_group;" ::: "memory");
}
__device__ __forceinline__ void cp_wait0() {
    asm volatile("cp.async.wait_group 0;" ::: "memory");
}
__device__ __forceinline__ void cp_wait1() {
    asm volatile("cp.async.wait_group 1;" ::: "memory");
}
__device__ __forceinline__ void cp_wait48() {
    asm volatile("cp.async.wait_group 48;" ::: "memory");
}
__device__ __forceinline__ uint32_t h2pack(float a, float b) {
    __half2 h = __floats2half2_rn(a, b);
    return *reinterpret_cast<uint32_t*>(&h);
}
__device__ __forceinline__ void ldsm4(uint32_t* r, uint32_t a) {
    asm volatile("ldmatrix.sync.aligned.m8n8.x4.shared.b16 {%0,%1,%2,%3}, [%4];"
                 : "=r"(r[0]), "=r"(r[1]), "=r"(r[2]), "=r"(r[3]) : "r"(a));
}
__device__ __forceinline__ void ldsm4t(uint32_t* r, uint32_t a) {
    asm volatile("ldmatrix.sync.aligned.m8n8.x4.trans.shared.b16 {%0,%1,%2,%3}, [%4];"
                 : "=r"(r[0]), "=r"(r[1]), "=r"(r[2]), "=r"(r[3]) : "r"(a));
}
__device__ __forceinline__ void mma16816(float* c, const uint32_t* a, const uint32_t* b) {
    asm volatile(
        "mma.sync.aligned.m16n8k16.row.col.f32.f16.f16.f32 "
        "{%0,%1,%2,%3}, {%4,%5,%6,%7}, {%8,%9}, {%0,%1,%2,%3};"
        : "+f"(c[0]), "+f"(c[1]), "+f"(c[2]), "+f"(c[3])
        : "r"(a[0]), "r"(a[1]), "r"(a[2]), "r"(a[3]), "r"(b[0]), "r"(b[1]));
}

// ---------------- stage 0: zero hists + transpose CHW->HWC (independent, fused) ----------------
__global__ void zeroTransK(const float* __restrict__ feat) {
    __shared__ float tile[32][33];
    int b = blockIdx.x, t = threadIdx.x;
    if (b < 256) {
        g_hist[b * 256 + t] = 0;
        if (b == 0) {
            g_hist256[t] = 0;
            if (t == 0) g_cnt = 0;
        }
        return;
    }
    int bb = b - 256;
    int bx = bb % 79, by = bb / 79;
    int tx = t & 31, ty = t >> 5;
    int p = bx * 32 + tx;
    int c = by * 32 + ty;
    #pragma unroll
    for (int j = 0; j < 32; j += 8)
        if (p < 2500 && (c + j) < FEAT_C)
            tile[ty + j][tx] = feat[(c + j) * 2500 + p];
    __syncthreads();
    int c2 = by * 32 + tx;
    int p2 = bx * 32 + ty;
    #pragma unroll
    for (int j = 0; j < 32; j += 8)
        if (c2 < FEAT_C && (p2 + j) < 2500)
            g_featT[(p2 + j) * FEAT_C + c2] = tile[tx][ty + j];
}

// ---------------- stage 1: score + key + 2-level histogram ----------------
__global__ void scoreK(const float* __restrict__ rois, const float* __restrict__ logits) {
    int i = blockIdx.x * blockDim.x + threadIdx.x;
    if (i >= N_ROIS) return;
    float y1 = fminf(fmaxf(rois[i * 4 + 0], 0.f), IMGSZ);
    float x1 = fminf(fmaxf(rois[i * 4 + 1], 0.f), IMGSZ);
    float y2 = fminf(fmaxf(rois[i * 4 + 2], 0.f), IMGSZ);
    float x2 = fminf(fmaxf(rois[i * 4 + 3], 0.f), IMGSZ);
    bool valid = ((y2 - y1) >= MIN_SIZE) && ((x2 - x1) >= MIN_SIZE);
    float l0 = logits[i * 2 + 0], l1 = logits[i * 2 + 1];
    float m = fmaxf(l0, l1);
    float e0 = expf(l0 - m), e1 = expf(l1 - m);
    float score = valid ? (e1 / (e0 + e1)) : -1.0f;
    unsigned b = __float_as_uint(score);
    unsigned key = (b & 0x80000000u) ? ~b : (b | 0x80000000u);
    g_keys[i] = ((unsigned long long)key << 32) | (unsigned)(~(unsigned)i);
    atomicAdd(&g_hist[key >> 16], 1);
    atomicAdd(&g_hist256[key >> 24], 1);
}

// ---------------- stage 2: threshold bin (2-level, 256 threads) ----------------
__global__ void threshK() {
    __shared__ int h[256];
    __shared__ int fine[256];
    __shared__ int cbS, aboveS;
    int t = threadIdx.x;  // 256
    h[t] = g_hist256[t];
    __syncthreads();
    if (t == 0) {
        int run = 0, sel = 0, above = 0;
        for (int b = 255; b >= 0; b--) {
            int ge = run + h[b];
            if (ge >= PRE_NMS && run < PRE_NMS) { sel = b; above = run; }
            run = ge;
        }
        cbS = sel; aboveS = above;
    }
    __syncthreads();
    int coarse = cbS;
    fine[t] = g_hist[coarse * 256 + t];
    __syncthreads();
    if (t == 0) {
        int run = aboveS;
        int sel = coarse * 256;
        for (int b = 255; b >= 0; b--) {
            int ge = run + fine[b];
            if (ge >= PRE_NMS && run < PRE_NMS) sel = coarse * 256 + b;
            run = ge;
        }
        g_threshBin = sel;
    }
}

// ---------------- stage 3: compact candidates ----------------
__global__ void compactK() {
    int i = blockIdx.x * blockDim.x + threadIdx.x;
    if (i >= N_ROIS) return;
    unsigned long long k = g_keys[i];
    if ((int)(k >> 48) >= g_threshBin) {
        int pos = atomicAdd(&g_cnt, 1);
        if (pos < SORT_N) g_cand[pos] = k;
    }
}

// ---------------- stage 4: parallel rank ----------------
__global__ void rankK(const float* __restrict__ rois) {
    __shared__ unsigned long long keys[SORT_N];
    int tid = threadIdx.x;  // 128
    int cnt = g_cnt; if (cnt > SORT_N) cnt = SORT_N;
    for (int i = tid; i < cnt; i += 128) keys[i] = g_cand[i];
    __syncthreads();
    int i = blockIdx.x * 128 + tid;
    if (i >= cnt) return;
    unsigned long long my = keys[i];
    int rank = 0;
    #pragma unroll 8
    for (int j = 0; j < cnt; j++) rank += (keys[j] > my);
    if (rank < PRE_NMS) {
        int idx = (int)(~(unsigned)my);
        g_boxes[rank * 4 + 0] = fminf(fmaxf(rois[idx * 4 + 0], 0.f), IMGSZ);
        g_boxes[rank * 4 + 1] = fminf(fmaxf(rois[idx * 4 + 1], 0.f), IMGSZ);
        g_boxes[rank * 4 + 2] = fminf(fmaxf(rois[idx * 4 + 2], 0.f), IMGSZ);
        g_boxes[rank * 4 + 3] = fminf(fmaxf(rois[idx * 4 + 3], 0.f), IMGSZ);
    }
}

// ---------------- stage 5: NMS IoU bitmask (upper triangle only) ----------------
// Scan consumes mask[i] bits only for j>i; zeroing j<=i bits is exact NMS semantics.
__global__ void nmsMaskK() {
    __shared__ float col[64][4];
    int t = threadIdx.x;
    int cbase = blockIdx.x * 64;
    int rbase = blockIdx.y * 64;
    int row = rbase + t;
    if (cbase + 63 < rbase) {           // entirely j < i: no bits needed
        if (row < PRE_NMS) g_mask[row * 32 + blockIdx.x] = 0ULL;
        return;
    }
    if (cbase + t < PRE_NMS) {
        col[t][0] = g_boxes[(cbase + t) * 4 + 0];
        col[t][1] = g_boxes[(cbase + t) * 4 + 1];
        col[t][2] = g_boxes[(cbase + t) * 4 + 2];
        col[t][3] = g_boxes[(cbase + t) * 4 + 3];
    } else {
        col[t][0] = col[t][1] = col[t][2] = col[t][3] = 0.f;
    }
    __syncthreads();
    if (row >= PRE_NMS) return;
    float ry1 = g_boxes[row * 4 + 0], rx1 = g_boxes[row * 4 + 1];
    float ry2 = g_boxes[row * 4 + 2], rx2 = g_boxes[row * 4 + 3];
    float ra = (ry2 - ry1) * (rx2 - rx1);
    unsigned long long bits = 0;
    #pragma unroll 8
    for (int j = 0; j < 64; j++) {
        int c = cbase + j;
        if (c >= PRE_NMS || c <= row) continue;   // j>i only
        float ca = (col[j][2] - col[j][0]) * (col[j][3] - col[j][1]);
        float yy1 = fmaxf(ry1, col[j][0]);
        float xx1 = fmaxf(rx1, col[j][1]);
        float yy2 = fminf(ry2, col[j][2]);
        float xx2 = fminf(rx2, col[j][3]);
        float inter = fmaxf(yy2 - yy1, 0.f) * fmaxf(xx2 - xx1, 0.f);
        float iou = inter / (ra + ca - inter + 1e-9f);
        if (iou > IOU_TH) bits |= (1ull << j);
    }
    g_mask[row * 32 + blockIdx.x] = bits;
}

// ---------------- stage 6: NMS scan with cp.async prefetch ring ----------------
__global__ void nmsScanK(float* __restrict__ out) {
    __shared__ __align__(16) unsigned long long ring[64][32];
    __shared__ unsigned char keptFlag[PRE_NMS];
    int lane = threadIdx.x;  // 32 threads
    for (int i = lane; i < PRE_NMS; i += 32) keptFlag[i] = 0;
    uint32_t rb = smem_u32(&ring[0][0]);
    for (int r = 0; r < 64; r++) {
        cpasync8(rb + ((uint32_t)r * 32 + lane) * 8, &g_mask[(size_t)r * 32 + lane]);
        cp_commit();
    }
    __syncwarp();
    unsigned long long remv = 0;
    int cnt = 0;
    for (int i = 0; i < PRE_NMS; i++) {
        unsigned long long w = __shfl_sync(0xffffffffu, remv, i >> 6);
        if (!((w >> (i & 63)) & 1ull)) {
            cp_wait48();
            remv |= ring[i & 63][lane];
            if (cnt < POST_NMS && lane == 0) { g_keep[cnt] = i; keptFlag[i] = 1; }
            cnt++;
            if (cnt == POST_NMS) break;
        }
        int nf = i + 64;
        if (nf < PRE_NMS)
            cpasync8(rb + ((uint32_t)(nf & 63) * 32 + lane) * 8, &g_mask[(size_t)nf * 32 + lane]);
        cp_commit();
    }
    cp_wait0();
    __syncwarp();
    if (lane == 0 && cnt < POST_NMS) {
        int extras[POST_NMS]; int ne = 0;
        for (int i = 0; i < PRE_NMS && ne < POST_NMS - cnt; i++)
            if (!keptFlag[i]) extras[ne++] = i;
        int merged[POST_NMS]; int a = 0, b = 0;
        for (int o = 0; o < POST_NMS; o++) {
            int va = (a < cnt) ? g_keep[a] : 0x7fffffff;
            int vb = (b < ne) ? extras[b] : 0x7fffffff;
            if (va < vb) { merged[o] = va; a++; } else { merged[o] = vb; b++; }
        }
        for (int o = 0; o < POST_NMS; o++) g_keep[o] = merged[o];
    }
    __syncwarp();
    for (int r = lane; r < POST_NMS; r += 32) {
        int idx = g_keep[r];
        #pragma unroll
        for (int j = 0; j < 4; j++) {
            float v = g_boxes[idx * 4 + j];
            g_roisKept[r * 4 + j] = v;
            out[OFF_ROIS + r * 4 + j] = v;
        }
    }
}

// ---------------- stage 8: ROI align (emits fp16) ----------------
__global__ void roiAlignK() {
    int r = blockIdx.x;
    __shared__ float box[4];
    __shared__ int sy0[14], sy1[14], sx0[14], sx1[14];
    __shared__ float sly[14], slx[14];
    int t = threadIdx.x;
    if (t < 4) box[t] = g_roisKept[r * 4 + t] * (1.0f / 16.0f);
    __syncthreads();
    if (t < 28) {
        int d = t / 14, g = t % 14;
        float c1 = d ? box[1] : box[0];
        float c2 = d ? box[3] : box[2];
        float bsz = fmaxf(c2 - c1, 1.0f) * (1.0f / 7.0f);
        float gg = ((float)g + 0.5f) * 0.5f;
        float s = c1 + gg * bsz;
        s = fminf(fmaxf(s, 0.0f), 49.0f);
        float s0 = floorf(s);
        int i0 = (int)s0;
        int i1 = min(i0 + 1, 49);
        float l = s - s0;
        if (d == 0) { sy0[g] = i0; sy1[g] = i1; sly[g] = l; }
        else        { sx0[g] = i0; sx1[g] = i1; slx[g] = l; }
    }
    __syncthreads();
    __half* outp = g_A1 + (size_t)r * D_IN;
    for (int c = t; c < FEAT_C; c += 256) {
        #pragma unroll
        for (int oy = 0; oy < 7; oy++) {
            #pragma unroll
            for (int ox = 0; ox < 7; ox++) {
                float acc = 0.f;
                #pragma unroll
                for (int sy = 0; sy < 2; sy++) {
                    #pragma unroll
                    for (int sx = 0; sx < 2; sx++) {
                        int i = oy * 2 + sy, j = ox * 2 + sx;
                        int y0 = sy0[i], y1 = sy1[i], x0 = sx0[j], x1 = sx1[j];
                        float ly = sly[i], lx = slx[j];
                        const float* f = g_featT;
                        float v00 = f[(y0 * 50 + x0) * FEAT_C + c];
                        float v01 = f[(y0 * 50 + x1) * FEAT_C + c];
                        float v10 = f[(y1 * 50 + x0) * FEAT_C + c];
                        float v11 = f[(y1 * 50 + x1) * FEAT_C + c];
                        acc += (1.f - ly) * ((1.f - lx) * v00 + lx * v01)
                             + ly * ((1.f - lx) * v10 + lx * v11);
                    }
                }
                outp[(oy * 7 + ox) * FEAT_C + c] = __float2half_rn(acc * 0.25f);
            }
        }
    }
}

// ================= HMMA FC kernel (fp16, deep cp.async pipeline) =================
// smem: A double 2x16KB @0, Braw double 2x32KB (64 rows x 512B) @32768, Bh 16KB @98304.
// A issued 1 chunk ahead, Braw 2 ahead; cp.async.wait_group 1 at top guarantees A(c), Braw(c).
#define FC_KC     64
#define FC_A1OFF  16384
#define FC_BRAW   32768
#define FC_BH     98304
#define FC_SMEM   114688
#define SWZ(o) ((o) ^ (((o) >> 3) & 0x70))

template <int PERM>
__global__ __launch_bounds__(256, 2) void fcHmmaK(
    const __half* __restrict__ A, const float* __restrict__ B,
    float* __restrict__ part, int K, int chunksPerCta)
{
    extern __shared__ char smem[];
    uint32_t sb = smem_u32(smem);
    int tid = threadIdx.x, wid = tid >> 5, lane = tid & 31;
    int mw = wid & 1, nw = wid >> 1;
    int n0 = blockIdx.x * 128;
    int ksp = blockIdx.y;
    int kbase = ksp * chunksPerCta * FC_KC;

    float acc[4][4][4] = {};

    int mat = lane >> 3, r8 = lane & 7;
    int rowA = mw * 64 + (mat & 1) * 8 + r8;
    uint32_t aRowOff = (uint32_t)rowA * 128;
    uint32_t aXor = (uint32_t)(rowA & 7) << 4;
    uint32_t aKb = (uint32_t)(mat >> 1) * 16;
    int krow = (mat & 1) * 8 + r8;
    uint32_t bXorBase = (uint32_t)r8 << 4;

    auto stageA = [&](int ci) {
        int k0 = kbase + ci * FC_KC;
        uint32_t abuf = sb + ((ci & 1) ? FC_A1OFF : 0);
        #pragma unroll
        for (int e = 0; e < 4; e++) {
            int flat = tid + e * 256;
            int seg = flat & 7, row = flat >> 3;
            cpasync16(abuf + SWZ((uint32_t)row * 128 + seg * 16),
                      A + (size_t)row * K + k0 + seg * 8);
        }
    };
    auto stageB = [&](int ci) {
        int k0 = kbase + ci * FC_KC;
        uint32_t bbuf = sb + FC_BRAW + ((ci & 1) ? 32768u : 0u);
        #pragma unroll
        for (int e = 0; e < 8; e++) {
            int flat = tid + e * 256;
            int row = flat >> 5, c16 = flat & 31;
            int gk = k0 + row;
            int grow = PERM ? ((gk & 511) * 49 + (gk >> 9)) : gk;
            cpasync16(bbuf + (uint32_t)row * 512 + c16 * 16,
                      B + (size_t)grow * D_H + n0 + c16 * 4);
        }
    };

    // prologue: group1 = {A0, B0}; group2 = {B1}
    stageA(0); stageB(0); cp_commit();
    if (chunksPerCta > 1) stageB(1);
    cp_commit();

    for (int c = 0; c < chunksPerCta; c++) {
        cp_wait1();
        __syncthreads();
        // convert Braw[c&1] fp32 -> Bh fp16 (SW128)
        const char* braw = smem + FC_BRAW + ((c & 1) ? 32768 : 0);
        #pragma unroll
        for (int e = 0; e < 8; e++) {
            int flat = tid + e * 256;
            int n4 = flat & 31, k = flat >> 5;
            float4 v = *(const float4*)(braw + (uint32_t)k * 512 + n4 * 16);
            uint32_t p0 = h2pack(v.x, v.y);
            uint32_t p1 = h2pack(v.z, v.w);
            uint32_t off = ((n4 >= 16) ? 8192u : 0u) + SWZ((uint32_t)k * 128 + (n4 & 15) * 8);
            sts64(sb + FC_BH + off, p0, p1);
        }
        __syncthreads();
        if (c + 1 < chunksPerCta) stageA(c + 1);
        cp_commit();
        if (c + 2 < chunksPerCta) stageB(c + 2);
        cp_commit();

        uint32_t abase = sb + ((c & 1) ? FC_A1OFF : 0);
        #pragma unroll
        for (int ks = 0; ks < 4; ks++) {
            uint32_t a16[4][4], b16[2][4];
            #pragma unroll
            for (int ti = 0; ti < 4; ti++)
                ldsm4(a16[ti], abase + aRowOff + (uint32_t)ti * 2048
                               + (((uint32_t)(ks * 32) + aKb) ^ aXor));
            uint32_t bRow = (uint32_t)(ks * 16 + krow) * 128;
            #pragma unroll
            for (int G = 0; G < 2; G++) {
                int ngg = nw * 4 + G * 2 + (mat >> 1);
                uint32_t off = (uint32_t)(ngg >> 3) * 8192 + bRow
                             + (((uint32_t)(ngg & 7) * 16) ^ bXorBase);
                ldsm4t(b16[G], sb + FC_BH + off);
            }
            #pragma unroll
            for (int ti = 0; ti < 4; ti++)
                #pragma unroll
                for (int tj = 0; tj < 4; tj++)
                    mma16816(acc[ti][tj], a16[ti], &b16[tj >> 1][(tj & 1) * 2]);
        }
    }

    int g = lane >> 2, t4 = lane & 3;
    float* pbase = part + ((size_t)ksp * 128) * D_H + n0;
    #pragma unroll
    for (int ti = 0; ti < 4; ti++) {
        int m = mw * 64 + ti * 16 + g;
        #pragma unroll
        for (int tj = 0; tj < 4; tj++) {
            int n = nw * 32 + tj * 8 + t4 * 2;
            float2 v0 = make_float2(acc[ti][tj][0], acc[ti][tj][1]);
            float2 v1 = make_float2(acc[ti][tj][2], acc[ti][tj][3]);
            *(float2*)(pbase + (size_t)m * D_H + n) = v0;
            *(float2*)(pbase + (size_t)(m + 8) * D_H + n) = v1;
        }
    }
}

// ---------------- reduce partials (float4 vectorized) ----------------
__global__ void reduce1K(const float* __restrict__ part, const float* __restrict__ bias,
                         __half* __restrict__ oh) {
    int idx4 = blockIdx.x * blockDim.x + threadIdx.x;
    if (idx4 >= POST_NMS * D_H / 4) return;
    int n4 = idx4 & (D_H / 4 - 1);
    float4 s = *(const float4*)(bias + n4 * 4);
    #pragma unroll
    for (int p = 0; p < 8; p++) {
        float4 v = *(const float4*)(part + (size_t)p * (POST_NMS * D_H) + idx4 * 4);
        s.x += v.x; s.y += v.y; s.z += v.z; s.w += v.w;
    }
    __half2 h0 = __floats2half2_rn(s.x, s.y);
    __half2 h1 = __floats2half2_rn(s.z, s.w);
    *(uint2*)(oh + idx4 * 4) = make_uint2(*(uint32_t*)&h0, *(uint32_t*)&h1);
}

__global__ void reduce2K(const float* __restrict__ part, const float* __restrict__ bias,
                         float* __restrict__ o) {
    int idx4 = blockIdx.x * blockDim.x + threadIdx.x;
    if (idx4 >= POST_NMS * D_H / 4) return;
    int n4 = idx4 & (D_H / 4 - 1);
    float4 s = *(const float4*)(bias + n4 * 4);
    #pragma unroll
    for (int p = 0; p < 8; p++) {
        float4 v = *(const float4*)(part + (size_t)p * (POST_NMS * D_H) + idx4 * 4);
        s.x += v.x; s.y += v.y; s.z += v.z; s.w += v.w;
    }
    *(float4*)(o + idx4 * 4) = s;
}

// ---------------- heads: fused cls+delta split-K SIMT GEMM ----------------
__global__ __launch_bounds__(256) void headK(
    const float* __restrict__ A, const float* __restrict__ Wc,
    const float* __restrict__ Wd, float* __restrict__ partC,
    float* __restrict__ partD)
{
    __shared__ float As[16][68];
    __shared__ float Bs[16][68];
    const float* W; float* part; int N, bn;
    if (blockIdx.x == 0) { W = Wc; part = partC; N = NC; bn = 0; }
    else { W = Wd; part = partD; N = NC * 4; bn = (blockIdx.x - 1) * 64; }
    int bm = blockIdx.y * 64;
    int kLen = 512;
    int k0base = blockIdx.z * kLen;
    int tid = threadIdx.x;
    int tx = tid & 15, ty = tid >> 4;
    float acc[4][4] = {};
    for (int k0 = 0; k0 < kLen; k0 += 16) {
        #pragma unroll
        for (int e = 0; e < 4; e++) {
            int flat = tid + e * 256;
            int m = flat >> 4, kk = flat & 15;
            As[kk][m] = A[(bm + m) * D_H + k0base + k0 + kk];
        }
        #pragma unroll
        for (int e = 0; e < 4; e++) {
            int flat = tid + e * 256;
            int kk = flat >> 6, n = flat & 63;
            int gn = bn + n;
            Bs[kk][n] = (gn < N) ? W[(size_t)(k0base + k0 + kk) * N + gn] : 0.0f;
        }
        __syncthreads();
        #pragma unroll
        for (int kk = 0; kk < 16; kk++) {
            float a[4], b[4];
            #pragma unroll
            for (int i = 0; i < 4; i++) a[i] = As[kk][ty * 4 + i];
            #pragma unroll
            for (int j = 0; j < 4; j++) b[j] = Bs[kk][tx * 4 + j];
            #pragma unroll
            for (int i = 0; i < 4; i++)
                #pragma unroll
                for (int j = 0; j < 4; j++)
                    acc[i][j] = fmaf(a[i], b[j], acc[i][j]);
        }
        __syncthreads();
    }
    #pragma unroll
    for (int i = 0; i < 4; i++) {
        int gm = bm + ty * 4 + i;
        #pragma unroll
        for (int j = 0; j < 4; j++) {
            int gn = bn + tx * 4 + j;
            if (gn < N) part[(size_t)blockIdx.z * 128 * N + gm * N + gn] = acc[i][j];
        }
    }
}

__global__ void headRedK(const float* __restrict__ partC, const float* __restrict__ partD,
                         const float* __restrict__ bc, const float* __restrict__ bd,
                         float* __restrict__ out) {
    int idx = blockIdx.x * blockDim.x + threadIdx.x;
    if (idx >= 128 * 105) return;
    int r = idx / 105, c = idx % 105;
    if (c < NC) {
        float s = bc[c];
        #pragma unroll
        for (int p = 0; p < 8; p++) s += partC[p * 128 * NC + r * NC + c];
        out[r * NC + c] = s;
    } else {
        int cd = c - NC;
        float s = bd[cd];
        #pragma unroll
        for (int p = 0; p < 8; p++) s += partD[p * 128 * NC * 4 + r * NC * 4 + cd];
        out[OFF_DELTAS + r * NC * 4 + cd] = s;
    }
}

// ---------------- launcher ----------------
extern "C" void kernel_launch(void* const* d_in, const int* in_sizes, int n_in,
                              void* d_out, int out_size)
{
    const float* features = (const float*)d_in[0];
    const float* rois     = (const float*)d_in[1];
    const float* logits   = (const float*)d_in[2];
    const float* W1 = (const float*)d_in[3];
    const float* b1 = (const float*)d_in[4];
    const float* W2 = (const float*)d_in[5];
    const float* b2 = (const float*)d_in[6];
    const float* Wc = (const float*)d_in[7];
    const float* bc = (const float*)d_in[8];
    const float* Wd = (const float*)d_in[9];
    const float* bd = (const float*)d_in[10];
    float* out = (float*)d_out;

    __half* A1; cudaGetSymbolAddress((void**)&A1, g_A1);
    __half* A2; cudaGetSymbolAddress((void**)&A2, g_A2);
    float* part; cudaGetSymbolAddress((void**)&part, g_part);
    float* h2;   cudaGetSymbolAddress((void**)&h2, g_h2);

    cudaFuncSetAttribute(fcHmmaK<1>, cudaFuncAttributeMaxDynamicSharedMemorySize, FC_SMEM);
    cudaFuncSetAttribute(fcHmmaK<0>, cudaFuncAttributeMaxDynamicSharedMemorySize, FC_SMEM);

    zeroTransK<<<256 + 79 * 16, 256>>>(features);
    scoreK<<<(N_ROIS + 255) / 256, 256>>>(rois, logits);
    threshK<<<1, 256>>>();
    compactK<<<(N_ROIS + 255) / 256, 256>>>();
    rankK<<<32, 128>>>(rois);
    nmsMaskK<<<dim3(32, 32), 64>>>();
    nmsScanK<<<1, 32>>>(out);
    roiAlignK<<<POST_NMS, 256>>>();

    // FC1: K=25088 = 8 ksplits * 49 chunks * 64
    fcHmmaK<1><<<dim3(32, 8), 256, FC_SMEM>>>(A1, W1, part, D_IN, 49);
    reduce1K<<<(POST_NMS * D_H / 4 + 255) / 256, 256>>>(part, b1, A2);

    // FC2: K=4096 = 8 ksplits * 8 chunks * 64
    fcHmmaK<0><<<dim3(32, 8), 256, FC_SMEM>>>(A2, W2, part, D_H, 8);
    reduce2K<<<(POST_NMS * D_H / 4 + 255) / 256, 256>>>(part, b2, h2);

    // heads: fused cls (x=0) + delta (x=1,2), split-K 8 x 512
    headK<<<dim3(3, 2, 8), 256>>>(h2, Wc, Wd, part, part + (1 << 21));
    headRedK<<<(128 * 105 + 255) / 256, 256>>>(part, part + (1 << 21), bc, bd, out);
}